// round 3
// baseline (speedup 1.0000x reference)
#include <cuda_runtime.h>
#include <math.h>

typedef unsigned long long u64t;

#define EM1 4
#define NN 64
#define FF 32
#define U1C 128
#define U2C 64
#define UAC 128
#define NT 512
#define BATCH 2048

// pitches: all multiples of 4 floats (16B) for vector ops; bank patterns verified
#define ADJ_PITCH 68
#define NODE_PITCH 36
#define AN_PITCH 36
#define H1_PITCH 132
#define P2_PITCH 68
#define H2_PITCH 68

#define OFF_ADJ 0                                   // 4*64*68  = 17408
#define OFF_NODE (OFF_ADJ + EM1*NN*ADJ_PITCH)       // 17408 (+64*36=2304)
#define OFF_RS   (OFF_NODE + NN*NODE_PITCH)         // 19712 (+256)
#define OFF_H1   (OFF_RS + EM1*NN)                  // 19968 (+64*132=8448)
#define OFF_U    (OFF_H1 + NN*H1_PITCH)             // 28416 (an[4][64][36] / pre2[4][64][68] union = 17408)
#define OFF_H2   (OFF_U + EM1*NN*P2_PITCH)          // 45824 (+64*68=4352)
#define OFF_RED  (OFF_H2 + NN*H2_PITCH)             // 50176 (+512)
#define SMEM_FLOATS (OFF_RED + 4*UAC)               // 50688
#define SMEM_BYTES (SMEM_FLOATS * 4)                // 202752 B

// ---- packed fp32x2 (Blackwell f32x2 pipe: 2x FFMA rate) ----
__device__ __forceinline__ u64t ffma2(u64t acc, u64t w, u64t a2) {
    u64t r;
    asm("fma.rn.f32x2 %0, %1, %2, %3;" : "=l"(r) : "l"(w), "l"(a2), "l"(acc));
    return r;
}
__device__ __forceinline__ u64t splat2(float a) {
    u64t r; asm("mov.b64 %0, {%1, %1};" : "=l"(r) : "f"(a)); return r;
}
__device__ __forceinline__ float2 unpack2(u64t v) {
    float2 f; asm("mov.b64 {%0, %1}, %2;" : "=f"(f.x), "=f"(f.y) : "l"(v)); return f;
}
__device__ __forceinline__ float sigmoidf_(float x) { return 1.0f / (1.0f + expf(-x)); }

__global__ void __launch_bounds__(NT, 1)
encoder_kernel(const float* __restrict__ adjacency,
               const float* __restrict__ node,
               const float* __restrict__ W1, const float* __restrict__ b1,
               const float* __restrict__ V1, const float* __restrict__ c1,
               const float* __restrict__ W2, const float* __restrict__ b2,
               const float* __restrict__ V2, const float* __restrict__ c2,
               const float* __restrict__ Wi, const float* __restrict__ bi,
               const float* __restrict__ Wj, const float* __restrict__ bj,
               float* __restrict__ out)
{
    extern __shared__ float smem[];
    const int b = blockIdx.x;
    const int tid = threadIdx.x;

    // ---------------- Phase A: stage adjacency (transposed, drop edge 0) + node ----------
    {
        const float* adjB = adjacency + (size_t)b * (NN * NN * 5);
        for (int idx = tid; idx < NN * NN * 5; idx += NT) {
            float v = adjB[idx];
            int e = idx % 5;
            int r = idx / 5;           // r = m*64 + n
            if (e > 0)
                smem[OFF_ADJ + ((e - 1) * NN + (r >> 6)) * ADJ_PITCH + (r & 63)] = v;
        }
        const float* nodeB = node + (size_t)b * (NN * FF);
        for (int idx = tid; idx < NN * FF; idx += NT)
            smem[OFF_NODE + (idx >> 5) * NODE_PITCH + (idx & 31)] = nodeB[idx];
    }
    __syncthreads();

    // ---------------- Phase B: an[e][m][f] = adj_e @ node ; rowsum[e][m] -----------------
    // thread: 2 m's x 8 f's.   per n: 2 LDS.32 + 2 LDS.128 feed 8 FFMA2
    {
        const int fg = tid & 3, row = tid >> 2;
        const int e = row >> 5, mg = row & 31;
        const int m0 = mg * 2;
        const int f0 = fg * 8;
        u64t acc0[4], acc1[4];
        #pragma unroll
        for (int i = 0; i < 4; i++) { acc0[i] = 0ull; acc1[i] = 0ull; }
        float rs0 = 0.0f, rs1 = 0.0f;
        const float* adj0 = &smem[OFF_ADJ + (e * NN + m0) * ADJ_PITCH];
        const float* nodep = &smem[OFF_NODE + f0];
        #pragma unroll 4
        for (int n = 0; n < NN; n++) {
            float a0 = adj0[n];
            float a1 = adj0[ADJ_PITCH + n];
            rs0 += a0; rs1 += a1;
            u64t s0 = splat2(a0), s1 = splat2(a1);
            ulonglong2 v0 = *(const ulonglong2*)(nodep + n * NODE_PITCH);
            ulonglong2 v1 = *(const ulonglong2*)(nodep + n * NODE_PITCH + 4);
            acc0[0] = ffma2(acc0[0], v0.x, s0); acc0[1] = ffma2(acc0[1], v0.y, s0);
            acc0[2] = ffma2(acc0[2], v1.x, s0); acc0[3] = ffma2(acc0[3], v1.y, s0);
            acc1[0] = ffma2(acc1[0], v0.x, s1); acc1[1] = ffma2(acc1[1], v0.y, s1);
            acc1[2] = ffma2(acc1[2], v1.x, s1); acc1[3] = ffma2(acc1[3], v1.y, s1);
        }
        float* an0 = &smem[OFF_U + (e * NN + m0) * AN_PITCH + f0];
        *(ulonglong2*)an0       = make_ulonglong2(acc0[0], acc0[1]);
        *(ulonglong2*)(an0 + 4) = make_ulonglong2(acc0[2], acc0[3]);
        float* an1 = an0 + AN_PITCH;
        *(ulonglong2*)an1       = make_ulonglong2(acc1[0], acc1[1]);
        *(ulonglong2*)(an1 + 4) = make_ulonglong2(acc1[2], acc1[3]);
        if (fg == 0) {
            smem[OFF_RS + e * NN + m0]     = rs0;
            smem[OFF_RS + e * NN + m0 + 1] = rs1;
        }
    }
    __syncthreads();

    // ---------------- Phase C: h1[m][u]=tanh(sum_e an_e@W1_e + rs_e*b1_e + node@V1 + c1) --
    // thread: m in {mg, mg+32}, 8 u's.  per f: 2 LDG.128 + 2 LDS.32 feed 8 FFMA2
    {
        const int ug = tid & 15, mg = tid >> 4;
        const int u0 = ug * 8;
        u64t acc[2][4];
        {
            ulonglong2 cA = *(const ulonglong2*)(c1 + u0);
            ulonglong2 cB = *(const ulonglong2*)(c1 + u0 + 4);
            #pragma unroll
            for (int im = 0; im < 2; im++) {
                acc[im][0] = cA.x; acc[im][1] = cA.y;
                acc[im][2] = cB.x; acc[im][3] = cB.y;
            }
        }
        #pragma unroll 1
        for (int e = 0; e < EM1; e++) {
            const float* anb = &smem[OFF_U + (e * NN + mg) * AN_PITCH];
            const float* w1b = W1 + e * FF * U1C + u0;
            #pragma unroll 4
            for (int f = 0; f < FF; f++) {
                ulonglong2 w0 = *(const ulonglong2*)(w1b + f * U1C);
                ulonglong2 w1v = *(const ulonglong2*)(w1b + f * U1C + 4);
                u64t a0 = splat2(anb[f]);
                u64t a1 = splat2(anb[32 * AN_PITCH + f]);
                acc[0][0] = ffma2(acc[0][0], w0.x, a0); acc[0][1] = ffma2(acc[0][1], w0.y, a0);
                acc[0][2] = ffma2(acc[0][2], w1v.x, a0); acc[0][3] = ffma2(acc[0][3], w1v.y, a0);
                acc[1][0] = ffma2(acc[1][0], w0.x, a1); acc[1][1] = ffma2(acc[1][1], w0.y, a1);
                acc[1][2] = ffma2(acc[1][2], w1v.x, a1); acc[1][3] = ffma2(acc[1][3], w1v.y, a1);
            }
        }
        #pragma unroll
        for (int e = 0; e < EM1; e++) {
            ulonglong2 w0 = *(const ulonglong2*)(b1 + e * U1C + u0);
            ulonglong2 w1v = *(const ulonglong2*)(b1 + e * U1C + u0 + 4);
            u64t a0 = splat2(smem[OFF_RS + e * NN + mg]);
            u64t a1 = splat2(smem[OFF_RS + e * NN + mg + 32]);
            acc[0][0] = ffma2(acc[0][0], w0.x, a0); acc[0][1] = ffma2(acc[0][1], w0.y, a0);
            acc[0][2] = ffma2(acc[0][2], w1v.x, a0); acc[0][3] = ffma2(acc[0][3], w1v.y, a0);
            acc[1][0] = ffma2(acc[1][0], w0.x, a1); acc[1][1] = ffma2(acc[1][1], w0.y, a1);
            acc[1][2] = ffma2(acc[1][2], w1v.x, a1); acc[1][3] = ffma2(acc[1][3], w1v.y, a1);
        }
        #pragma unroll 4
        for (int f = 0; f < FF; f++) {
            ulonglong2 w0 = *(const ulonglong2*)(V1 + f * U1C + u0);
            ulonglong2 w1v = *(const ulonglong2*)(V1 + f * U1C + u0 + 4);
            u64t a0 = splat2(smem[OFF_NODE + mg * NODE_PITCH + f]);
            u64t a1 = splat2(smem[OFF_NODE + (mg + 32) * NODE_PITCH + f]);
            acc[0][0] = ffma2(acc[0][0], w0.x, a0); acc[0][1] = ffma2(acc[0][1], w0.y, a0);
            acc[0][2] = ffma2(acc[0][2], w1v.x, a0); acc[0][3] = ffma2(acc[0][3], w1v.y, a0);
            acc[1][0] = ffma2(acc[1][0], w0.x, a1); acc[1][1] = ffma2(acc[1][1], w0.y, a1);
            acc[1][2] = ffma2(acc[1][2], w1v.x, a1); acc[1][3] = ffma2(acc[1][3], w1v.y, a1);
        }
        #pragma unroll
        for (int im = 0; im < 2; im++) {
            int m = mg + im * 32;
            float* h = &smem[OFF_H1 + m * H1_PITCH + u0];
            float2 x0 = unpack2(acc[im][0]), x1 = unpack2(acc[im][1]);
            float2 x2 = unpack2(acc[im][2]), x3 = unpack2(acc[im][3]);
            float4 o0 = make_float4(tanhf(x0.x), tanhf(x0.y), tanhf(x1.x), tanhf(x1.y));
            float4 o1 = make_float4(tanhf(x2.x), tanhf(x2.y), tanhf(x3.x), tanhf(x3.y));
            *(float4*)h = o0;
            *(float4*)(h + 4) = o1;
        }
    }
    __syncthreads();

    // ---------------- Phase D: pre2[e][n][u] = [h1,node][n] @ W2[e] + b2[e] ---------------
    // thread: n in {ng, ng+16, ng+32, ng+48}, 8 u's.  per k: 2 LDG.128 + 4 LDS.32 -> 16 FFMA2
    {
        const int e = tid >> 7, r = tid & 127;
        const int ug = r & 7, ng = r >> 3;
        const int u0 = ug * 8;
        u64t acc[4][4];
        {
            ulonglong2 bA = *(const ulonglong2*)(b2 + e * U2C + u0);
            ulonglong2 bB = *(const ulonglong2*)(b2 + e * U2C + u0 + 4);
            #pragma unroll
            for (int in = 0; in < 4; in++) {
                acc[in][0] = bA.x; acc[in][1] = bA.y;
                acc[in][2] = bB.x; acc[in][3] = bB.y;
            }
        }
        const float* w2b = W2 + e * (U1C + FF) * U2C + u0;
        const float* h1b = &smem[OFF_H1 + ng * H1_PITCH];
        #pragma unroll 2
        for (int k = 0; k < U1C; k++) {
            ulonglong2 w0 = *(const ulonglong2*)(w2b + k * U2C);
            ulonglong2 w1v = *(const ulonglong2*)(w2b + k * U2C + 4);
            #pragma unroll
            for (int in = 0; in < 4; in++) {
                u64t a2 = splat2(h1b[in * 16 * H1_PITCH + k]);
                acc[in][0] = ffma2(acc[in][0], w0.x, a2);
                acc[in][1] = ffma2(acc[in][1], w0.y, a2);
                acc[in][2] = ffma2(acc[in][2], w1v.x, a2);
                acc[in][3] = ffma2(acc[in][3], w1v.y, a2);
            }
        }
        const float* nb = &smem[OFF_NODE + ng * NODE_PITCH];
        #pragma unroll 2
        for (int k = 0; k < FF; k++) {
            ulonglong2 w0 = *(const ulonglong2*)(w2b + (U1C + k) * U2C);
            ulonglong2 w1v = *(const ulonglong2*)(w2b + (U1C + k) * U2C + 4);
            #pragma unroll
            for (int in = 0; in < 4; in++) {
                u64t a2 = splat2(nb[in * 16 * NODE_PITCH + k]);
                acc[in][0] = ffma2(acc[in][0], w0.x, a2);
                acc[in][1] = ffma2(acc[in][1], w0.y, a2);
                acc[in][2] = ffma2(acc[in][2], w1v.x, a2);
                acc[in][3] = ffma2(acc[in][3], w1v.y, a2);
            }
        }
        #pragma unroll
        for (int in = 0; in < 4; in++) {
            int row = e * NN + ng + 16 * in;
            float* dst = &smem[OFF_U + row * P2_PITCH + u0];
            *(ulonglong2*)dst       = make_ulonglong2(acc[in][0], acc[in][1]);
            *(ulonglong2*)(dst + 4) = make_ulonglong2(acc[in][2], acc[in][3]);
        }
    }
    __syncthreads();

    // ---------------- Phase E: h2[m][u] = tanh(sum_e adj_e @ pre2_e + node@V2 + c2) -------
    // thread: m in {mg, mg+32}, 4 u's. per n-quad: 2 LDS.128 (adj) + 4 LDS.128 (pre2) -> 16 FFMA2
    {
        const int ug = tid & 15, mg = tid >> 4;
        const int u0 = ug * 4;
        u64t acc[2][2];
        {
            ulonglong2 cA = *(const ulonglong2*)(c2 + u0);
            acc[0][0] = cA.x; acc[0][1] = cA.y;
            acc[1][0] = cA.x; acc[1][1] = cA.y;
        }
        #pragma unroll 1
        for (int e = 0; e < EM1; e++) {
            const float* adjm0 = &smem[OFF_ADJ + (e * NN + mg) * ADJ_PITCH];
            const float* adjm1 = adjm0 + 32 * ADJ_PITCH;
            const float* p2 = &smem[OFF_U + e * NN * P2_PITCH + u0];
            #pragma unroll 2
            for (int q = 0; q < 16; q++) {
                float4 a0 = *(const float4*)(adjm0 + q * 4);
                float4 a1 = *(const float4*)(adjm1 + q * 4);
                const float* p2q = p2 + (q * 4) * P2_PITCH;
                ulonglong2 w0 = *(const ulonglong2*)(p2q);
                ulonglong2 w1 = *(const ulonglong2*)(p2q + P2_PITCH);
                ulonglong2 w2v = *(const ulonglong2*)(p2q + 2 * P2_PITCH);
                ulonglong2 w3 = *(const ulonglong2*)(p2q + 3 * P2_PITCH);
                u64t s;
                s = splat2(a0.x); acc[0][0] = ffma2(acc[0][0], w0.x, s); acc[0][1] = ffma2(acc[0][1], w0.y, s);
                s = splat2(a0.y); acc[0][0] = ffma2(acc[0][0], w1.x, s); acc[0][1] = ffma2(acc[0][1], w1.y, s);
                s = splat2(a0.z); acc[0][0] = ffma2(acc[0][0], w2v.x, s); acc[0][1] = ffma2(acc[0][1], w2v.y, s);
                s = splat2(a0.w); acc[0][0] = ffma2(acc[0][0], w3.x, s); acc[0][1] = ffma2(acc[0][1], w3.y, s);
                s = splat2(a1.x); acc[1][0] = ffma2(acc[1][0], w0.x, s); acc[1][1] = ffma2(acc[1][1], w0.y, s);
                s = splat2(a1.y); acc[1][0] = ffma2(acc[1][0], w1.x, s); acc[1][1] = ffma2(acc[1][1], w1.y, s);
                s = splat2(a1.z); acc[1][0] = ffma2(acc[1][0], w2v.x, s); acc[1][1] = ffma2(acc[1][1], w2v.y, s);
                s = splat2(a1.w); acc[1][0] = ffma2(acc[1][0], w3.x, s); acc[1][1] = ffma2(acc[1][1], w3.y, s);
            }
        }
        #pragma unroll 4
        for (int f = 0; f < FF; f++) {
            ulonglong2 w0 = *(const ulonglong2*)(V2 + f * U2C + u0);
            u64t a0 = splat2(smem[OFF_NODE + mg * NODE_PITCH + f]);
            u64t a1 = splat2(smem[OFF_NODE + (mg + 32) * NODE_PITCH + f]);
            acc[0][0] = ffma2(acc[0][0], w0.x, a0); acc[0][1] = ffma2(acc[0][1], w0.y, a0);
            acc[1][0] = ffma2(acc[1][0], w0.x, a1); acc[1][1] = ffma2(acc[1][1], w0.y, a1);
        }
        #pragma unroll
        for (int im = 0; im < 2; im++) {
            int m = mg + im * 32;
            float2 x0 = unpack2(acc[im][0]), x1 = unpack2(acc[im][1]);
            float4 o = make_float4(tanhf(x0.x), tanhf(x0.y), tanhf(x1.x), tanhf(x1.y));
            *(float4*)&smem[OFF_H2 + m * H2_PITCH + u0] = o;
        }
    }
    __syncthreads();

    // ---------------- Phase F: gates -------------------------------------------------------
    // thread: n in {ng, ng+32}, 8 u's for both i and j. per k: 4 LDG.128 + 2 LDS.32 -> 16 FFMA2
    {
        const int ug = tid & 15, ng = tid >> 4;
        const int u0 = ug * 8;
        u64t ai[2][4], aj[2][4];
        {
            ulonglong2 bA = *(const ulonglong2*)(bi + u0);
            ulonglong2 bB = *(const ulonglong2*)(bi + u0 + 4);
            ulonglong2 cA = *(const ulonglong2*)(bj + u0);
            ulonglong2 cB = *(const ulonglong2*)(bj + u0 + 4);
            #pragma unroll
            for (int in = 0; in < 2; in++) {
                ai[in][0] = bA.x; ai[in][1] = bA.y; ai[in][2] = bB.x; ai[in][3] = bB.y;
                aj[in][0] = cA.x; aj[in][1] = cA.y; aj[in][2] = cB.x; aj[in][3] = cB.y;
            }
        }
        const float* h2b = &smem[OFF_H2 + ng * H2_PITCH];
        #pragma unroll 2
        for (int k = 0; k < U2C; k++) {
            ulonglong2 wi0 = *(const ulonglong2*)(Wi + k * UAC + u0);
            ulonglong2 wi1 = *(const ulonglong2*)(Wi + k * UAC + u0 + 4);
            ulonglong2 wj0 = *(const ulonglong2*)(Wj + k * UAC + u0);
            ulonglong2 wj1 = *(const ulonglong2*)(Wj + k * UAC + u0 + 4);
            u64t a0 = splat2(h2b[k]);
            u64t a1 = splat2(h2b[32 * H2_PITCH + k]);
            ai[0][0] = ffma2(ai[0][0], wi0.x, a0); ai[0][1] = ffma2(ai[0][1], wi0.y, a0);
            ai[0][2] = ffma2(ai[0][2], wi1.x, a0); ai[0][3] = ffma2(ai[0][3], wi1.y, a0);
            aj[0][0] = ffma2(aj[0][0], wj0.x, a0); aj[0][1] = ffma2(aj[0][1], wj0.y, a0);
            aj[0][2] = ffma2(aj[0][2], wj1.x, a0); aj[0][3] = ffma2(aj[0][3], wj1.y, a0);
            ai[1][0] = ffma2(ai[1][0], wi0.x, a1); ai[1][1] = ffma2(ai[1][1], wi0.y, a1);
            ai[1][2] = ffma2(ai[1][2], wi1.x, a1); ai[1][3] = ffma2(ai[1][3], wi1.y, a1);
            aj[1][0] = ffma2(aj[1][0], wj0.x, a1); aj[1][1] = ffma2(aj[1][1], wj0.y, a1);
            aj[1][2] = ffma2(aj[1][2], wj1.x, a1); aj[1][3] = ffma2(aj[1][3], wj1.y, a1);
        }
        const float* nb = &smem[OFF_NODE + ng * NODE_PITCH];
        #pragma unroll 2
        for (int k = 0; k < FF; k++) {
            ulonglong2 wi0 = *(const ulonglong2*)(Wi + (U2C + k) * UAC + u0);
            ulonglong2 wi1 = *(const ulonglong2*)(Wi + (U2C + k) * UAC + u0 + 4);
            ulonglong2 wj0 = *(const ulonglong2*)(Wj + (U2C + k) * UAC + u0);
            ulonglong2 wj1 = *(const ulonglong2*)(Wj + (U2C + k) * UAC + u0 + 4);
            u64t a0 = splat2(nb[k]);
            u64t a1 = splat2(nb[32 * NODE_PITCH + k]);
            ai[0][0] = ffma2(ai[0][0], wi0.x, a0); ai[0][1] = ffma2(ai[0][1], wi0.y, a0);
            ai[0][2] = ffma2(ai[0][2], wi1.x, a0); ai[0][3] = ffma2(ai[0][3], wi1.y, a0);
            aj[0][0] = ffma2(aj[0][0], wj0.x, a0); aj[0][1] = ffma2(aj[0][1], wj0.y, a0);
            aj[0][2] = ffma2(aj[0][2], wj1.x, a0); aj[0][3] = ffma2(aj[0][3], wj1.y, a0);
            ai[1][0] = ffma2(ai[1][0], wi0.x, a1); ai[1][1] = ffma2(ai[1][1], wi0.y, a1);
            ai[1][2] = ffma2(ai[1][2], wi1.x, a1); ai[1][3] = ffma2(ai[1][3], wi1.y, a1);
            aj[1][0] = ffma2(aj[1][0], wj0.x, a1); aj[1][1] = ffma2(aj[1][1], wj0.y, a1);
            aj[1][2] = ffma2(aj[1][2], wj1.x, a1); aj[1][3] = ffma2(aj[1][3], wj1.y, a1);
        }
        #pragma unroll
        for (int in = 0; in < 2; in++) {
            int n = ng + in * 32;
            float* pr = &smem[OFF_H1 + n * H1_PITCH + u0];   // prod reuses dead h1 region
            float2 i0 = unpack2(ai[in][0]), i1 = unpack2(ai[in][1]);
            float2 i2 = unpack2(ai[in][2]), i3 = unpack2(ai[in][3]);
            float2 j0 = unpack2(aj[in][0]), j1 = unpack2(aj[in][1]);
            float2 j2 = unpack2(aj[in][2]), j3 = unpack2(aj[in][3]);
            float4 o0 = make_float4(sigmoidf_(i0.x) * tanhf(j0.x),
                                    sigmoidf_(i0.y) * tanhf(j0.y),
                                    sigmoidf_(i1.x) * tanhf(j1.x),
                                    sigmoidf_(i1.y) * tanhf(j1.y));
            float4 o1 = make_float4(sigmoidf_(i2.x) * tanhf(j2.x),
                                    sigmoidf_(i2.y) * tanhf(j2.y),
                                    sigmoidf_(i3.x) * tanhf(j3.x),
                                    sigmoidf_(i3.y) * tanhf(j3.y));
            *(float4*)pr = o0;
            *(float4*)(pr + 4) = o1;
        }
    }
    __syncthreads();

    // ---------------- Phase G: out[b][u] = tanh(sum_n prod[n][u]) --------------------------
    {
        const int q = tid >> 7;
        const int u = tid & 127;
        float s = 0.0f;
        #pragma unroll
        for (int i = 0; i < 16; i++)
            s += smem[OFF_H1 + (q * 16 + i) * H1_PITCH + u];
        smem[OFF_RED + q * UAC + u] = s;
    }
    __syncthreads();
    if (tid < UAC) {
        float s = smem[OFF_RED + tid] + smem[OFF_RED + UAC + tid]
                + smem[OFF_RED + 2 * UAC + tid] + smem[OFF_RED + 3 * UAC + tid];
        out[(size_t)b * UAC + tid] = tanhf(s);
    }
}

extern "C" void kernel_launch(void* const* d_in, const int* in_sizes, int n_in,
                              void* d_out, int out_size) {
    (void)in_sizes; (void)n_in; (void)out_size;
    const float* adjacency = (const float*)d_in[0];
    // d_in[1] = hidden (rank-2, unused by the encoder math)
    const float* node = (const float*)d_in[2];
    const float* W1 = (const float*)d_in[3];
    const float* b1 = (const float*)d_in[4];
    const float* V1 = (const float*)d_in[5];
    const float* c1 = (const float*)d_in[6];
    const float* W2 = (const float*)d_in[7];
    const float* b2 = (const float*)d_in[8];
    const float* V2 = (const float*)d_in[9];
    const float* c2 = (const float*)d_in[10];
    const float* Wi = (const float*)d_in[11];
    const float* bi = (const float*)d_in[12];
    const float* Wj = (const float*)d_in[13];
    const float* bj = (const float*)d_in[14];

    cudaFuncSetAttribute(encoder_kernel,
                         cudaFuncAttributeMaxDynamicSharedMemorySize, SMEM_BYTES);
    encoder_kernel<<<BATCH, NT, SMEM_BYTES>>>(adjacency, node,
                                              W1, b1, V1, c1,
                                              W2, b2, V2, c2,
                                              Wi, bi, Wj, bj,
                                              (float*)d_out);
}

// round 4
// speedup vs baseline: 1.4082x; 1.4082x over previous
#include <cuda_runtime.h>
#include <math.h>

typedef unsigned long long u64t;

#define EM1 4
#define NN 64
#define FF 32
#define U1C 128
#define U2C 64
#define UAC 128
#define NT 512
#define BATCH 2048

// pitches: odd pitches for scalar-read arrays (conflict-free lane-varying reads),
// even/mult-4 pitches where vector accesses occur
#define ADJ_PITCH 65
#define NODE_PITCH 34
#define AN_PITCH 33
#define H1_PITCH 129
#define P2_PITCH 68
#define GP_PITCH 130
#define H2_PITCH 65

#define OFF_ADJ 0
#define OFF_NODE (OFF_ADJ + EM1*NN*ADJ_PITCH)    // 16640
#define OFF_RS   (OFF_NODE + NN*NODE_PITCH)      // 18816
#define OFF_H1   (OFF_RS + EM1*NN)               // 19072
#define OFF_U    (OFF_H1 + NN*H1_PITCH)          // 27328  (an 4*64*33 / pre2 4*64*68 / gates 128*130 union)
#define OFF_H2   (OFF_U + EM1*NN*P2_PITCH)       // 44736
#define OFF_RED  (OFF_H2 + NN*H2_PITCH)          // 48896
#define SMEM_FLOATS (OFF_RED + 4*UAC)            // 49408
#define SMEM_BYTES (SMEM_FLOATS * 4)             // 197632 B

// ---- packed fp32x2 (Blackwell f32x2 pipe: 2x FFMA rate) ----
__device__ __forceinline__ u64t ffma2(u64t acc, u64t w, u64t a2) {
    u64t r;
    asm("fma.rn.f32x2 %0, %1, %2, %3;" : "=l"(r) : "l"(w), "l"(a2), "l"(acc));
    return r;
}
__device__ __forceinline__ u64t splat2(float a) {
    u64t r; asm("mov.b64 %0, {%1, %1};" : "=l"(r) : "f"(a)); return r;
}
__device__ __forceinline__ float2 unpack2(u64t v) {
    float2 f; asm("mov.b64 {%0, %1}, %2;" : "=f"(f.x), "=f"(f.y) : "l"(v)); return f;
}
__device__ __forceinline__ float sigmoidf_(float x) { return 1.0f / (1.0f + expf(-x)); }

__global__ void __launch_bounds__(NT, 1)
encoder_kernel(const float* __restrict__ adjacency,
               const float* __restrict__ node,
               const float* __restrict__ W1, const float* __restrict__ b1,
               const float* __restrict__ V1, const float* __restrict__ c1,
               const float* __restrict__ W2, const float* __restrict__ b2,
               const float* __restrict__ V2, const float* __restrict__ c2,
               const float* __restrict__ Wi, const float* __restrict__ bi,
               const float* __restrict__ Wj, const float* __restrict__ bj,
               float* __restrict__ out)
{
    extern __shared__ float smem[];
    const int b = blockIdx.x;
    const int tid = threadIdx.x;

    // ---------------- Phase A: stage adjacency (transposed, drop edge 0) + node ----------
    {
        const float* adjB = adjacency + (size_t)b * (NN * NN * 5);
        for (int idx = tid; idx < NN * NN * 5; idx += NT) {
            float v = adjB[idx];
            int e = idx % 5;
            int r = idx / 5;           // r = m*64 + n
            if (e > 0)
                smem[OFF_ADJ + ((e - 1) * NN + (r >> 6)) * ADJ_PITCH + (r & 63)] = v;
        }
        const float* nodeB = node + (size_t)b * (NN * FF);
        for (int idx = tid; idx < NN * FF; idx += NT)
            smem[OFF_NODE + (idx >> 5) * NODE_PITCH + (idx & 31)] = nodeB[idx];
    }
    __syncthreads();

    // ---------------- Phase B: an[e][m][f] = adj_e @ node ; rowsum[e][m] -----------------
    // thread: 4 m's x 4 f's. per n: 4 LDS.32 (adj, 4-addr bcast) + 2 LDS.64 (node, 8-addr) -> 8 FFMA2
    {
        const int e = tid >> 7;
        const int r = tid & 127;
        const int fg = r & 7;
        const int mg = r >> 3;
        const int f0 = fg * 4;
        const int m0 = mg * 4;
        u64t acc[4][2];
        #pragma unroll
        for (int im = 0; im < 4; im++) { acc[im][0] = 0ull; acc[im][1] = 0ull; }
        float rs[4] = {0.f, 0.f, 0.f, 0.f};
        const float* adjb = &smem[OFF_ADJ + (e * NN + m0) * ADJ_PITCH];
        const float* nodep = &smem[OFF_NODE + f0];
        #pragma unroll 4
        for (int n = 0; n < NN; n++) {
            u64t v0 = *(const u64t*)(nodep + n * NODE_PITCH);
            u64t v1 = *(const u64t*)(nodep + n * NODE_PITCH + 2);
            #pragma unroll
            for (int im = 0; im < 4; im++) {
                float a = adjb[im * ADJ_PITCH + n];
                rs[im] += a;
                u64t s = splat2(a);
                acc[im][0] = ffma2(acc[im][0], v0, s);
                acc[im][1] = ffma2(acc[im][1], v1, s);
            }
        }
        #pragma unroll
        for (int im = 0; im < 4; im++) {
            float* an = &smem[OFF_U + (e * NN + m0 + im) * AN_PITCH + f0];
            float2 x0 = unpack2(acc[im][0]), x1 = unpack2(acc[im][1]);
            an[0] = x0.x; an[1] = x0.y; an[2] = x1.x; an[3] = x1.y;
        }
        if (fg == 0) {
            #pragma unroll
            for (int im = 0; im < 4; im++)
                smem[OFF_RS + e * NN + m0 + im] = rs[im];
        }
    }
    __syncthreads();

    // ---------------- Phase C: h1[m][u]=tanh(sum_e an_e@W1_e + rs_e*b1_e + node@V1 + c1) --
    // lane: m (0..31) + m+32;  warp-uniform u-slice of 8.  per k: 2 LDG.128 bcast + 2 LDS.32 -> 8 FFMA2
    {
        const int ml = tid & 31;
        const int ug = tid >> 5;          // 0..15
        const int u0 = ug * 8;
        u64t acc[2][4];
        {
            ulonglong2 cA = *(const ulonglong2*)(c1 + u0);
            ulonglong2 cB = *(const ulonglong2*)(c1 + u0 + 4);
            #pragma unroll
            for (int im = 0; im < 2; im++) {
                acc[im][0] = cA.x; acc[im][1] = cA.y;
                acc[im][2] = cB.x; acc[im][3] = cB.y;
            }
        }
        #pragma unroll 1
        for (int e = 0; e < EM1; e++) {
            const float* anb = &smem[OFF_U + (e * NN + ml) * AN_PITCH];
            const float* w1b = W1 + e * FF * U1C + u0;
            #pragma unroll 4
            for (int f = 0; f < FF; f++) {
                ulonglong2 wA = *(const ulonglong2*)(w1b + f * U1C);
                ulonglong2 wB = *(const ulonglong2*)(w1b + f * U1C + 4);
                u64t a0 = splat2(anb[f]);
                u64t a1 = splat2(anb[32 * AN_PITCH + f]);
                acc[0][0] = ffma2(acc[0][0], wA.x, a0); acc[0][1] = ffma2(acc[0][1], wA.y, a0);
                acc[0][2] = ffma2(acc[0][2], wB.x, a0); acc[0][3] = ffma2(acc[0][3], wB.y, a0);
                acc[1][0] = ffma2(acc[1][0], wA.x, a1); acc[1][1] = ffma2(acc[1][1], wA.y, a1);
                acc[1][2] = ffma2(acc[1][2], wB.x, a1); acc[1][3] = ffma2(acc[1][3], wB.y, a1);
            }
        }
        #pragma unroll
        for (int e = 0; e < EM1; e++) {
            ulonglong2 wA = *(const ulonglong2*)(b1 + e * U1C + u0);
            ulonglong2 wB = *(const ulonglong2*)(b1 + e * U1C + u0 + 4);
            u64t a0 = splat2(smem[OFF_RS + e * NN + ml]);
            u64t a1 = splat2(smem[OFF_RS + e * NN + ml + 32]);
            acc[0][0] = ffma2(acc[0][0], wA.x, a0); acc[0][1] = ffma2(acc[0][1], wA.y, a0);
            acc[0][2] = ffma2(acc[0][2], wB.x, a0); acc[0][3] = ffma2(acc[0][3], wB.y, a0);
            acc[1][0] = ffma2(acc[1][0], wA.x, a1); acc[1][1] = ffma2(acc[1][1], wA.y, a1);
            acc[1][2] = ffma2(acc[1][2], wB.x, a1); acc[1][3] = ffma2(acc[1][3], wB.y, a1);
        }
        #pragma unroll 4
        for (int f = 0; f < FF; f++) {
            ulonglong2 wA = *(const ulonglong2*)(V1 + f * U1C + u0);
            ulonglong2 wB = *(const ulonglong2*)(V1 + f * U1C + u0 + 4);
            u64t a0 = splat2(smem[OFF_NODE + ml * NODE_PITCH + f]);
            u64t a1 = splat2(smem[OFF_NODE + (ml + 32) * NODE_PITCH + f]);
            acc[0][0] = ffma2(acc[0][0], wA.x, a0); acc[0][1] = ffma2(acc[0][1], wA.y, a0);
            acc[0][2] = ffma2(acc[0][2], wB.x, a0); acc[0][3] = ffma2(acc[0][3], wB.y, a0);
            acc[1][0] = ffma2(acc[1][0], wA.x, a1); acc[1][1] = ffma2(acc[1][1], wA.y, a1);
            acc[1][2] = ffma2(acc[1][2], wB.x, a1); acc[1][3] = ffma2(acc[1][3], wB.y, a1);
        }
        #pragma unroll
        for (int im = 0; im < 2; im++) {
            int m = ml + im * 32;
            float* h = &smem[OFF_H1 + m * H1_PITCH + u0];
            float2 x0 = unpack2(acc[im][0]), x1 = unpack2(acc[im][1]);
            float2 x2 = unpack2(acc[im][2]), x3 = unpack2(acc[im][3]);
            h[0] = tanhf(x0.x); h[1] = tanhf(x0.y); h[2] = tanhf(x1.x); h[3] = tanhf(x1.y);
            h[4] = tanhf(x2.x); h[5] = tanhf(x2.y); h[6] = tanhf(x3.x); h[7] = tanhf(x3.y);
        }
    }
    __syncthreads();

    // ---------------- Phase D: pre2[e][n][u] = [h1,node][n] @ W2[e] + b2[e] ---------------
    // lane: 4 n's (stride 16); half-warp-uniform u-slice of 8. per k: 2 LDG.128 + 4 LDS.32 -> 16 FFMA2
    {
        const int e = tid >> 7;
        const int r = tid & 127;
        const int nl = r & 15;
        const int ug = r >> 4;            // 0..7
        const int u0 = ug * 8;
        u64t acc[4][4];
        {
            ulonglong2 bA = *(const ulonglong2*)(b2 + e * U2C + u0);
            ulonglong2 bB = *(const ulonglong2*)(b2 + e * U2C + u0 + 4);
            #pragma unroll
            for (int im = 0; im < 4; im++) {
                acc[im][0] = bA.x; acc[im][1] = bA.y;
                acc[im][2] = bB.x; acc[im][3] = bB.y;
            }
        }
        const float* w2b = W2 + e * (U1C + FF) * U2C + u0;
        const float* h1b = &smem[OFF_H1 + nl * H1_PITCH];
        #pragma unroll 2
        for (int k = 0; k < U1C; k++) {
            ulonglong2 wA = *(const ulonglong2*)(w2b + k * U2C);
            ulonglong2 wB = *(const ulonglong2*)(w2b + k * U2C + 4);
            #pragma unroll
            for (int im = 0; im < 4; im++) {
                u64t a = splat2(h1b[im * 16 * H1_PITCH + k]);
                acc[im][0] = ffma2(acc[im][0], wA.x, a);
                acc[im][1] = ffma2(acc[im][1], wA.y, a);
                acc[im][2] = ffma2(acc[im][2], wB.x, a);
                acc[im][3] = ffma2(acc[im][3], wB.y, a);
            }
        }
        const float* nb = &smem[OFF_NODE + nl * NODE_PITCH];
        #pragma unroll 2
        for (int k = 0; k < FF; k++) {
            ulonglong2 wA = *(const ulonglong2*)(w2b + (U1C + k) * U2C);
            ulonglong2 wB = *(const ulonglong2*)(w2b + (U1C + k) * U2C + 4);
            #pragma unroll
            for (int im = 0; im < 4; im++) {
                u64t a = splat2(nb[im * 16 * NODE_PITCH + k]);
                acc[im][0] = ffma2(acc[im][0], wA.x, a);
                acc[im][1] = ffma2(acc[im][1], wA.y, a);
                acc[im][2] = ffma2(acc[im][2], wB.x, a);
                acc[im][3] = ffma2(acc[im][3], wB.y, a);
            }
        }
        #pragma unroll
        for (int im = 0; im < 4; im++) {
            float* dst = &smem[OFF_U + (e * NN + nl + 16 * im) * P2_PITCH + u0];
            *(ulonglong2*)dst       = make_ulonglong2(acc[im][0], acc[im][1]);
            *(ulonglong2*)(dst + 4) = make_ulonglong2(acc[im][2], acc[im][3]);
        }
    }
    __syncthreads();

    // ---------------- Phase E: h2[m][u] = tanh(sum_e adj_e @ pre2_e + node@V2 + c2) -------
    // lane: m, m+32; warp-uniform u-slice of 4. per n: 2 LDS.32 (adj) + 1 LDS.128 bcast -> 4 FFMA2
    {
        const int ml = tid & 31;
        const int ug = tid >> 5;          // 0..15
        const int u0 = ug * 4;
        u64t acc[2][2];
        {
            ulonglong2 cA = *(const ulonglong2*)(c2 + u0);
            acc[0][0] = cA.x; acc[0][1] = cA.y;
            acc[1][0] = cA.x; acc[1][1] = cA.y;
        }
        #pragma unroll 1
        for (int e = 0; e < EM1; e++) {
            const float* adjb = &smem[OFF_ADJ + (e * NN + ml) * ADJ_PITCH];
            const float* p2b = &smem[OFF_U + e * NN * P2_PITCH + u0];
            #pragma unroll 4
            for (int n = 0; n < NN; n++) {
                ulonglong2 w = *(const ulonglong2*)(p2b + n * P2_PITCH);
                u64t a0 = splat2(adjb[n]);
                u64t a1 = splat2(adjb[32 * ADJ_PITCH + n]);
                acc[0][0] = ffma2(acc[0][0], w.x, a0); acc[0][1] = ffma2(acc[0][1], w.y, a0);
                acc[1][0] = ffma2(acc[1][0], w.x, a1); acc[1][1] = ffma2(acc[1][1], w.y, a1);
            }
        }
        #pragma unroll 4
        for (int f = 0; f < FF; f++) {
            ulonglong2 w = *(const ulonglong2*)(V2 + f * U2C + u0);
            u64t a0 = splat2(smem[OFF_NODE + ml * NODE_PITCH + f]);
            u64t a1 = splat2(smem[OFF_NODE + (ml + 32) * NODE_PITCH + f]);
            acc[0][0] = ffma2(acc[0][0], w.x, a0); acc[0][1] = ffma2(acc[0][1], w.y, a0);
            acc[1][0] = ffma2(acc[1][0], w.x, a1); acc[1][1] = ffma2(acc[1][1], w.y, a1);
        }
        #pragma unroll
        for (int im = 0; im < 2; im++) {
            int m = ml + im * 32;
            float* h = &smem[OFF_H2 + m * H2_PITCH + u0];
            float2 x0 = unpack2(acc[im][0]), x1 = unpack2(acc[im][1]);
            h[0] = tanhf(x0.x); h[1] = tanhf(x0.y); h[2] = tanhf(x1.x); h[3] = tanhf(x1.y);
        }
    }
    __syncthreads();

    // ---------------- Phase F: gate pre-activations ----------------------------------------
    // thread-half picks matrix (i or j); lane: 4 n's (stride 16); u-slice of 8.
    // per k: 2 LDG.128 + 4 LDS.32 -> 16 FFMA2. pre-acts stored to OFF_U (pre2 is dead).
    {
        const int mat = tid >> 8;         // 0 -> Wi/bi, 1 -> Wj/bj
        const int r = tid & 255;
        const int nl = r & 15;
        const int ug = r >> 4;            // 0..15
        const int u0 = ug * 8;
        const float* W = mat ? Wj : Wi;
        const float* bv = mat ? bj : bi;
        u64t acc[4][4];
        {
            ulonglong2 bA = *(const ulonglong2*)(bv + u0);
            ulonglong2 bB = *(const ulonglong2*)(bv + u0 + 4);
            #pragma unroll
            for (int im = 0; im < 4; im++) {
                acc[im][0] = bA.x; acc[im][1] = bA.y;
                acc[im][2] = bB.x; acc[im][3] = bB.y;
            }
        }
        const float* h2b = &smem[OFF_H2 + nl * H2_PITCH];
        #pragma unroll 2
        for (int k = 0; k < U2C; k++) {
            ulonglong2 wA = *(const ulonglong2*)(W + k * UAC + u0);
            ulonglong2 wB = *(const ulonglong2*)(W + k * UAC + u0 + 4);
            #pragma unroll
            for (int im = 0; im < 4; im++) {
                u64t a = splat2(h2b[im * 16 * H2_PITCH + k]);
                acc[im][0] = ffma2(acc[im][0], wA.x, a);
                acc[im][1] = ffma2(acc[im][1], wA.y, a);
                acc[im][2] = ffma2(acc[im][2], wB.x, a);
                acc[im][3] = ffma2(acc[im][3], wB.y, a);
            }
        }
        const float* nb = &smem[OFF_NODE + nl * NODE_PITCH];
        #pragma unroll 2
        for (int k = 0; k < FF; k++) {
            ulonglong2 wA = *(const ulonglong2*)(W + (U2C + k) * UAC + u0);
            ulonglong2 wB = *(const ulonglong2*)(W + (U2C + k) * UAC + u0 + 4);
            #pragma unroll
            for (int im = 0; im < 4; im++) {
                u64t a = splat2(nb[im * 16 * NODE_PITCH + k]);
                acc[im][0] = ffma2(acc[im][0], wA.x, a);
                acc[im][1] = ffma2(acc[im][1], wA.y, a);
                acc[im][2] = ffma2(acc[im][2], wB.x, a);
                acc[im][3] = ffma2(acc[im][3], wB.y, a);
            }
        }
        #pragma unroll
        for (int im = 0; im < 4; im++) {
            u64t* dst = (u64t*)&smem[OFF_U + (mat * NN + nl + 16 * im) * GP_PITCH + u0];
            dst[0] = acc[im][0]; dst[1] = acc[im][1];
            dst[2] = acc[im][2]; dst[3] = acc[im][3];
        }
    }
    __syncthreads();

    // ---------------- Phase G: out[b][u] = tanh(sum_n sigmoid(pi)*tanh(pj)) ----------------
    {
        const int q = tid >> 7;           // 0..3
        const int u = tid & 127;
        float s = 0.0f;
        #pragma unroll
        for (int i = 0; i < 16; i++) {
            int n = q * 16 + i;
            float pi = smem[OFF_U + n * GP_PITCH + u];
            float pj = smem[OFF_U + (NN + n) * GP_PITCH + u];
            s += sigmoidf_(pi) * tanhf(pj);
        }
        smem[OFF_RED + q * UAC + u] = s;
    }
    __syncthreads();
    if (tid < UAC) {
        float s = smem[OFF_RED + tid] + smem[OFF_RED + UAC + tid]
                + smem[OFF_RED + 2 * UAC + tid] + smem[OFF_RED + 3 * UAC + tid];
        out[(size_t)b * UAC + tid] = tanhf(s);
    }
}

extern "C" void kernel_launch(void* const* d_in, const int* in_sizes, int n_in,
                              void* d_out, int out_size) {
    (void)in_sizes; (void)n_in; (void)out_size;
    const float* adjacency = (const float*)d_in[0];
    // d_in[1] = hidden (rank-2, unused by the encoder math)
    const float* node = (const float*)d_in[2];
    const float* W1 = (const float*)d_in[3];
    const float* b1 = (const float*)d_in[4];
    const float* V1 = (const float*)d_in[5];
    const float* c1 = (const float*)d_in[6];
    const float* W2 = (const float*)d_in[7];
    const float* b2 = (const float*)d_in[8];
    const float* V2 = (const float*)d_in[9];
    const float* c2 = (const float*)d_in[10];
    const float* Wi = (const float*)d_in[11];
    const float* bi = (const float*)d_in[12];
    const float* Wj = (const float*)d_in[13];
    const float* bj = (const float*)d_in[14];

    cudaFuncSetAttribute(encoder_kernel,
                         cudaFuncAttributeMaxDynamicSharedMemorySize, SMEM_BYTES);
    encoder_kernel<<<BATCH, NT, SMEM_BYTES>>>(adjacency, node,
                                              W1, b1, V1, c1,
                                              W2, b2, V2, c2,
                                              Wi, bi, Wj, bj,
                                              (float*)d_out);
}

// round 5
// speedup vs baseline: 1.4936x; 1.0606x over previous
#include <cuda_runtime.h>
#include <math.h>

typedef unsigned long long u64t;

#define EM1 4
#define NN 64
#define FF 32
#define U1C 128
#define U2C 64
#define UAC 128
#define NT 512
#define BATCH 2048

// pitches: arrays read vectorized-over-k need pitch % 4 == 0; adjacency stays odd (65)
// for conflict-free scalar lane-row access.
#define ADJ_PITCH 65
#define NODE_PITCH 36
#define AN_PITCH 36
#define H1_PITCH 132
#define P2_PITCH 68
#define GP_PITCH 130
#define H2_PITCH 68

#define OFF_ADJ 0
#define OFF_NODE (OFF_ADJ + EM1*NN*ADJ_PITCH)    // 16640
#define OFF_RS   (OFF_NODE + NN*NODE_PITCH)      // 18944
#define OFF_H1   (OFF_RS + EM1*NN)               // 19200
#define OFF_U    (OFF_H1 + NN*H1_PITCH)          // 27648 (an 4*64*36 / pre2 4*64*68 / gates 128*130)
#define OFF_H2   (OFF_U + EM1*NN*P2_PITCH)       // 45056
#define OFF_RED  (OFF_H2 + NN*H2_PITCH)          // 49408
#define SMEM_FLOATS (OFF_RED + 4*UAC)            // 49920
#define SMEM_BYTES (SMEM_FLOATS * 4)             // 199680 B

// ---- packed fp32x2 (Blackwell f32x2 pipe: 2x FFMA rate) ----
__device__ __forceinline__ u64t ffma2(u64t acc, u64t w, u64t a2) {
    u64t r;
    asm("fma.rn.f32x2 %0, %1, %2, %3;" : "=l"(r) : "l"(w), "l"(a2), "l"(acc));
    return r;
}
__device__ __forceinline__ u64t splat2(float a) {
    u64t r; asm("mov.b64 %0, {%1, %1};" : "=l"(r) : "f"(a)); return r;
}
__device__ __forceinline__ float2 unpack2(u64t v) {
    float2 f; asm("mov.b64 {%0, %1}, %2;" : "=f"(f.x), "=f"(f.y) : "l"(v)); return f;
}
__device__ __forceinline__ float sigmoidf_(float x) { return 1.0f / (1.0f + expf(-x)); }

__global__ void __launch_bounds__(NT, 1)
encoder_kernel(const float* __restrict__ adjacency,
               const float* __restrict__ node,
               const float* __restrict__ W1, const float* __restrict__ b1,
               const float* __restrict__ V1, const float* __restrict__ c1,
               const float* __restrict__ W2, const float* __restrict__ b2,
               const float* __restrict__ V2, const float* __restrict__ c2,
               const float* __restrict__ Wi, const float* __restrict__ bi,
               const float* __restrict__ Wj, const float* __restrict__ bj,
               float* __restrict__ out)
{
    extern __shared__ float smem[];
    const int b = blockIdx.x;
    const int tid = threadIdx.x;

    // ---------------- Phase A: stage adjacency (transposed, drop edge 0) + node ----------
    {
        const float* adjB = adjacency + (size_t)b * (NN * NN * 5);
        for (int idx = tid; idx < NN * NN * 5; idx += NT) {
            float v = adjB[idx];
            int e = idx % 5;
            int r = idx / 5;           // r = m*64 + n
            if (e > 0)
                smem[OFF_ADJ + ((e - 1) * NN + (r >> 6)) * ADJ_PITCH + (r & 63)] = v;
        }
        const float* nodeB = node + (size_t)b * (NN * FF);
        for (int idx = tid; idx < NN * FF; idx += NT)
            smem[OFF_NODE + (idx >> 5) * NODE_PITCH + (idx & 31)] = nodeB[idx];
    }
    __syncthreads();

    // ---------------- Phase B: an[e][m][f] = adj_e @ node ; rowsum[e][m] -----------------
    // thread: 4 m x 4 f. per n: 4 LDS.32 bcast (adj) + 2 LDS.64 (node) -> 8 FFMA2
    {
        const int e = tid >> 7;
        const int r = tid & 127;
        const int fg = r & 7;
        const int mg = r >> 3;
        const int f0 = fg * 4;
        const int m0 = mg * 4;
        u64t acc[4][2];
        #pragma unroll
        for (int im = 0; im < 4; im++) { acc[im][0] = 0ull; acc[im][1] = 0ull; }
        float rs[4] = {0.f, 0.f, 0.f, 0.f};
        const float* adjb = &smem[OFF_ADJ + (e * NN + m0) * ADJ_PITCH];
        const float* nodep = &smem[OFF_NODE + f0];
        #pragma unroll 4
        for (int n = 0; n < NN; n++) {
            u64t v0 = *(const u64t*)(nodep + n * NODE_PITCH);
            u64t v1 = *(const u64t*)(nodep + n * NODE_PITCH + 2);
            #pragma unroll
            for (int im = 0; im < 4; im++) {
                float a = adjb[im * ADJ_PITCH + n];
                rs[im] += a;
                u64t s = splat2(a);
                acc[im][0] = ffma2(acc[im][0], v0, s);
                acc[im][1] = ffma2(acc[im][1], v1, s);
            }
        }
        #pragma unroll
        for (int im = 0; im < 4; im++) {
            float* an = &smem[OFF_U + (e * NN + m0 + im) * AN_PITCH + f0];
            float2 x0 = unpack2(acc[im][0]), x1 = unpack2(acc[im][1]);
            *(float4*)an = make_float4(x0.x, x0.y, x1.x, x1.y);
        }
        if (fg == 0) {
            #pragma unroll
            for (int im = 0; im < 4; im++)
                smem[OFF_RS + e * NN + m0 + im] = rs[im];
        }
    }
    __syncthreads();

    // ---------------- Phase C: h1[m][u]=tanh(sum_e an_e@W1_e + rs_e*b1_e + node@V1 + c1) --
    // lane: m, m+32; warp-uniform u-slice of 8. acts vectorized over f (LDS.128 / 4f)
    {
        const int ml = tid & 31;
        const int ug = tid >> 5;          // 0..15
        const int u0 = ug * 8;
        u64t acc[2][4];
        {
            ulonglong2 cA = *(const ulonglong2*)(c1 + u0);
            ulonglong2 cB = *(const ulonglong2*)(c1 + u0 + 4);
            #pragma unroll
            for (int im = 0; im < 2; im++) {
                acc[im][0] = cA.x; acc[im][1] = cA.y;
                acc[im][2] = cB.x; acc[im][3] = cB.y;
            }
        }
        #pragma unroll 1
        for (int e = 0; e < EM1; e++) {
            const float* anb = &smem[OFF_U + (e * NN + ml) * AN_PITCH];
            const float* w1b = W1 + e * FF * U1C + u0;
            #pragma unroll 2
            for (int f4 = 0; f4 < FF; f4 += 4) {
                float a0[4], a1[4];
                *(float4*)a0 = *(const float4*)(anb + f4);
                *(float4*)a1 = *(const float4*)(anb + 32 * AN_PITCH + f4);
                #pragma unroll
                for (int j = 0; j < 4; j++) {
                    const float* wr = w1b + (f4 + j) * U1C;
                    ulonglong2 wA = *(const ulonglong2*)(wr);
                    ulonglong2 wB = *(const ulonglong2*)(wr + 4);
                    u64t s0 = splat2(a0[j]), s1 = splat2(a1[j]);
                    acc[0][0] = ffma2(acc[0][0], wA.x, s0); acc[0][1] = ffma2(acc[0][1], wA.y, s0);
                    acc[0][2] = ffma2(acc[0][2], wB.x, s0); acc[0][3] = ffma2(acc[0][3], wB.y, s0);
                    acc[1][0] = ffma2(acc[1][0], wA.x, s1); acc[1][1] = ffma2(acc[1][1], wA.y, s1);
                    acc[1][2] = ffma2(acc[1][2], wB.x, s1); acc[1][3] = ffma2(acc[1][3], wB.y, s1);
                }
            }
        }
        #pragma unroll
        for (int e = 0; e < EM1; e++) {
            ulonglong2 wA = *(const ulonglong2*)(b1 + e * U1C + u0);
            ulonglong2 wB = *(const ulonglong2*)(b1 + e * U1C + u0 + 4);
            u64t s0 = splat2(smem[OFF_RS + e * NN + ml]);
            u64t s1 = splat2(smem[OFF_RS + e * NN + ml + 32]);
            acc[0][0] = ffma2(acc[0][0], wA.x, s0); acc[0][1] = ffma2(acc[0][1], wA.y, s0);
            acc[0][2] = ffma2(acc[0][2], wB.x, s0); acc[0][3] = ffma2(acc[0][3], wB.y, s0);
            acc[1][0] = ffma2(acc[1][0], wA.x, s1); acc[1][1] = ffma2(acc[1][1], wA.y, s1);
            acc[1][2] = ffma2(acc[1][2], wB.x, s1); acc[1][3] = ffma2(acc[1][3], wB.y, s1);
        }
        {
            const float* nb0 = &smem[OFF_NODE + ml * NODE_PITCH];
            const float* nb1 = &smem[OFF_NODE + (ml + 32) * NODE_PITCH];
            #pragma unroll 2
            for (int f4 = 0; f4 < FF; f4 += 4) {
                float a0[4], a1[4];
                *(float4*)a0 = *(const float4*)(nb0 + f4);
                *(float4*)a1 = *(const float4*)(nb1 + f4);
                #pragma unroll
                for (int j = 0; j < 4; j++) {
                    const float* wr = V1 + (f4 + j) * U1C + u0;
                    ulonglong2 wA = *(const ulonglong2*)(wr);
                    ulonglong2 wB = *(const ulonglong2*)(wr + 4);
                    u64t s0 = splat2(a0[j]), s1 = splat2(a1[j]);
                    acc[0][0] = ffma2(acc[0][0], wA.x, s0); acc[0][1] = ffma2(acc[0][1], wA.y, s0);
                    acc[0][2] = ffma2(acc[0][2], wB.x, s0); acc[0][3] = ffma2(acc[0][3], wB.y, s0);
                    acc[1][0] = ffma2(acc[1][0], wA.x, s1); acc[1][1] = ffma2(acc[1][1], wA.y, s1);
                    acc[1][2] = ffma2(acc[1][2], wB.x, s1); acc[1][3] = ffma2(acc[1][3], wB.y, s1);
                }
            }
        }
        #pragma unroll
        for (int im = 0; im < 2; im++) {
            int m = ml + im * 32;
            float* h = &smem[OFF_H1 + m * H1_PITCH + u0];
            float2 x0 = unpack2(acc[im][0]), x1 = unpack2(acc[im][1]);
            float2 x2 = unpack2(acc[im][2]), x3 = unpack2(acc[im][3]);
            *(float4*)h       = make_float4(tanhf(x0.x), tanhf(x0.y), tanhf(x1.x), tanhf(x1.y));
            *(float4*)(h + 4) = make_float4(tanhf(x2.x), tanhf(x2.y), tanhf(x3.x), tanhf(x3.y));
        }
    }
    __syncthreads();

    // ---------------- Phase D: pre2[e][n][u] = [h1,node][n] @ W2[e] + b2[e] ---------------
    // lane: 4 n (stride 16); half-warp u-slice of 8. acts vectorized over k.
    {
        const int e = tid >> 7;
        const int r = tid & 127;
        const int nl = r & 15;
        const int ug = r >> 4;            // 0..7
        const int u0 = ug * 8;
        u64t acc[4][4];
        {
            ulonglong2 bA = *(const ulonglong2*)(b2 + e * U2C + u0);
            ulonglong2 bB = *(const ulonglong2*)(b2 + e * U2C + u0 + 4);
            #pragma unroll
            for (int im = 0; im < 4; im++) {
                acc[im][0] = bA.x; acc[im][1] = bA.y;
                acc[im][2] = bB.x; acc[im][3] = bB.y;
            }
        }
        const float* w2b = W2 + e * (U1C + FF) * U2C + u0;
        const float* h1b = &smem[OFF_H1 + nl * H1_PITCH];
        #pragma unroll 1
        for (int k4 = 0; k4 < U1C; k4 += 4) {
            float a[4][4];
            #pragma unroll
            for (int im = 0; im < 4; im++)
                *(float4*)a[im] = *(const float4*)(h1b + im * 16 * H1_PITCH + k4);
            #pragma unroll
            for (int j = 0; j < 4; j++) {
                const float* wr = w2b + (k4 + j) * U2C;
                ulonglong2 wA = *(const ulonglong2*)(wr);
                ulonglong2 wB = *(const ulonglong2*)(wr + 4);
                #pragma unroll
                for (int im = 0; im < 4; im++) {
                    u64t s = splat2(a[im][j]);
                    acc[im][0] = ffma2(acc[im][0], wA.x, s);
                    acc[im][1] = ffma2(acc[im][1], wA.y, s);
                    acc[im][2] = ffma2(acc[im][2], wB.x, s);
                    acc[im][3] = ffma2(acc[im][3], wB.y, s);
                }
            }
        }
        const float* nb = &smem[OFF_NODE + nl * NODE_PITCH];
        #pragma unroll 1
        for (int k4 = 0; k4 < FF; k4 += 4) {
            float a[4][4];
            #pragma unroll
            for (int im = 0; im < 4; im++)
                *(float4*)a[im] = *(const float4*)(nb + im * 16 * NODE_PITCH + k4);
            #pragma unroll
            for (int j = 0; j < 4; j++) {
                const float* wr = w2b + (U1C + k4 + j) * U2C;
                ulonglong2 wA = *(const ulonglong2*)(wr);
                ulonglong2 wB = *(const ulonglong2*)(wr + 4);
                #pragma unroll
                for (int im = 0; im < 4; im++) {
                    u64t s = splat2(a[im][j]);
                    acc[im][0] = ffma2(acc[im][0], wA.x, s);
                    acc[im][1] = ffma2(acc[im][1], wA.y, s);
                    acc[im][2] = ffma2(acc[im][2], wB.x, s);
                    acc[im][3] = ffma2(acc[im][3], wB.y, s);
                }
            }
        }
        #pragma unroll
        for (int im = 0; im < 4; im++) {
            float* dst = &smem[OFF_U + (e * NN + nl + 16 * im) * P2_PITCH + u0];
            *(ulonglong2*)dst       = make_ulonglong2(acc[im][0], acc[im][1]);
            *(ulonglong2*)(dst + 4) = make_ulonglong2(acc[im][2], acc[im][3]);
        }
    }
    __syncthreads();

    // ---------------- Phase E: h2[m][u] = tanh(sum_e adj_e @ pre2_e + node@V2 + c2) -------
    // lane: m, m+32; warp-uniform u-slice of 4. per n: 2 LDS.32 + 1 LDS.128 bcast -> 4 FFMA2
    {
        const int ml = tid & 31;
        const int ug = tid >> 5;          // 0..15
        const int u0 = ug * 4;
        u64t acc[2][2];
        {
            ulonglong2 cA = *(const ulonglong2*)(c2 + u0);
            acc[0][0] = cA.x; acc[0][1] = cA.y;
            acc[1][0] = cA.x; acc[1][1] = cA.y;
        }
        #pragma unroll 1
        for (int e = 0; e < EM1; e++) {
            const float* adjb = &smem[OFF_ADJ + (e * NN + ml) * ADJ_PITCH];
            const float* p2b = &smem[OFF_U + e * NN * P2_PITCH + u0];
            #pragma unroll 4
            for (int n = 0; n < NN; n++) {
                ulonglong2 w = *(const ulonglong2*)(p2b + n * P2_PITCH);
                u64t s0 = splat2(adjb[n]);
                u64t s1 = splat2(adjb[32 * ADJ_PITCH + n]);
                acc[0][0] = ffma2(acc[0][0], w.x, s0); acc[0][1] = ffma2(acc[0][1], w.y, s0);
                acc[1][0] = ffma2(acc[1][0], w.x, s1); acc[1][1] = ffma2(acc[1][1], w.y, s1);
            }
        }
        {
            const float* nb0 = &smem[OFF_NODE + ml * NODE_PITCH];
            const float* nb1 = &smem[OFF_NODE + (ml + 32) * NODE_PITCH];
            #pragma unroll 2
            for (int f4 = 0; f4 < FF; f4 += 4) {
                float a0[4], a1[4];
                *(float4*)a0 = *(const float4*)(nb0 + f4);
                *(float4*)a1 = *(const float4*)(nb1 + f4);
                #pragma unroll
                for (int j = 0; j < 4; j++) {
                    ulonglong2 w = *(const ulonglong2*)(V2 + (f4 + j) * U2C + u0);
                    u64t s0 = splat2(a0[j]), s1 = splat2(a1[j]);
                    acc[0][0] = ffma2(acc[0][0], w.x, s0); acc[0][1] = ffma2(acc[0][1], w.y, s0);
                    acc[1][0] = ffma2(acc[1][0], w.x, s1); acc[1][1] = ffma2(acc[1][1], w.y, s1);
                }
            }
        }
        #pragma unroll
        for (int im = 0; im < 2; im++) {
            int m = ml + im * 32;
            float* h = &smem[OFF_H2 + m * H2_PITCH + u0];
            float2 x0 = unpack2(acc[im][0]), x1 = unpack2(acc[im][1]);
            *(float4*)h = make_float4(tanhf(x0.x), tanhf(x0.y), tanhf(x1.x), tanhf(x1.y));
        }
    }
    __syncthreads();

    // ---------------- Phase F: gate pre-activations ----------------------------------------
    // thread-half picks matrix (i or j); lane: 4 n (stride 16); u-slice of 8; acts vector over k
    {
        const int mat = tid >> 8;         // 0 -> Wi/bi, 1 -> Wj/bj
        const int r = tid & 255;
        const int nl = r & 15;
        const int ug = r >> 4;            // 0..15
        const int u0 = ug * 8;
        const float* W = mat ? Wj : Wi;
        const float* bv = mat ? bj : bi;
        u64t acc[4][4];
        {
            ulonglong2 bA = *(const ulonglong2*)(bv + u0);
            ulonglong2 bB = *(const ulonglong2*)(bv + u0 + 4);
            #pragma unroll
            for (int im = 0; im < 4; im++) {
                acc[im][0] = bA.x; acc[im][1] = bA.y;
                acc[im][2] = bB.x; acc[im][3] = bB.y;
            }
        }
        const float* h2b = &smem[OFF_H2 + nl * H2_PITCH];
        #pragma unroll 1
        for (int k4 = 0; k4 < U2C; k4 += 4) {
            float a[4][4];
            #pragma unroll
            for (int im = 0; im < 4; im++)
                *(float4*)a[im] = *(const float4*)(h2b + im * 16 * H2_PITCH + k4);
            #pragma unroll
            for (int j = 0; j < 4; j++) {
                const float* wr = W + (k4 + j) * UAC + u0;
                ulonglong2 wA = *(const ulonglong2*)(wr);
                ulonglong2 wB = *(const ulonglong2*)(wr + 4);
                #pragma unroll
                for (int im = 0; im < 4; im++) {
                    u64t s = splat2(a[im][j]);
                    acc[im][0] = ffma2(acc[im][0], wA.x, s);
                    acc[im][1] = ffma2(acc[im][1], wA.y, s);
                    acc[im][2] = ffma2(acc[im][2], wB.x, s);
                    acc[im][3] = ffma2(acc[im][3], wB.y, s);
                }
            }
        }
        const float* nb = &smem[OFF_NODE + nl * NODE_PITCH];
        #pragma unroll 1
        for (int k4 = 0; k4 < FF; k4 += 4) {
            float a[4][4];
            #pragma unroll
            for (int im = 0; im < 4; im++)
                *(float4*)a[im] = *(const float4*)(nb + im * 16 * NODE_PITCH + k4);
            #pragma unroll
            for (int j = 0; j < 4; j++) {
                const float* wr = W + (U2C + k4 + j) * UAC + u0;
                ulonglong2 wA = *(const ulonglong2*)(wr);
                ulonglong2 wB = *(const ulonglong2*)(wr + 4);
                #pragma unroll
                for (int im = 0; im < 4; im++) {
                    u64t s = splat2(a[im][j]);
                    acc[im][0] = ffma2(acc[im][0], wA.x, s);
                    acc[im][1] = ffma2(acc[im][1], wA.y, s);
                    acc[im][2] = ffma2(acc[im][2], wB.x, s);
                    acc[im][3] = ffma2(acc[im][3], wB.y, s);
                }
            }
        }
        #pragma unroll
        for (int im = 0; im < 4; im++) {
            u64t* dst = (u64t*)&smem[OFF_U + (mat * NN + nl + 16 * im) * GP_PITCH + u0];
            dst[0] = acc[im][0]; dst[1] = acc[im][1];
            dst[2] = acc[im][2]; dst[3] = acc[im][3];
        }
    }
    __syncthreads();

    // ---------------- Phase G: out[b][u] = tanh(sum_n sigmoid(pi)*tanh(pj)) ----------------
    {
        const int q = tid >> 7;           // 0..3
        const int u = tid & 127;
        float s = 0.0f;
        #pragma unroll
        for (int i = 0; i < 16; i++) {
            int n = q * 16 + i;
            float pi = smem[OFF_U + n * GP_PITCH + u];
            float pj = smem[OFF_U + (NN + n) * GP_PITCH + u];
            s += sigmoidf_(pi) * tanhf(pj);
        }
        smem[OFF_RED + q * UAC + u] = s;
    }
    __syncthreads();
    if (tid < UAC) {
        float s = smem[OFF_RED + tid] + smem[OFF_RED + UAC + tid]
                + smem[OFF_RED + 2 * UAC + tid] + smem[OFF_RED + 3 * UAC + tid];
        out[(size_t)b * UAC + tid] = tanhf(s);
    }
}

extern "C" void kernel_launch(void* const* d_in, const int* in_sizes, int n_in,
                              void* d_out, int out_size) {
    (void)in_sizes; (void)n_in; (void)out_size;
    const float* adjacency = (const float*)d_in[0];
    // d_in[1] = hidden (rank-2, unused by the encoder math)
    const float* node = (const float*)d_in[2];
    const float* W1 = (const float*)d_in[3];
    const float* b1 = (const float*)d_in[4];
    const float* V1 = (const float*)d_in[5];
    const float* c1 = (const float*)d_in[6];
    const float* W2 = (const float*)d_in[7];
    const float* b2 = (const float*)d_in[8];
    const float* V2 = (const float*)d_in[9];
    const float* c2 = (const float*)d_in[10];
    const float* Wi = (const float*)d_in[11];
    const float* bi = (const float*)d_in[12];
    const float* Wj = (const float*)d_in[13];
    const float* bj = (const float*)d_in[14];

    cudaFuncSetAttribute(encoder_kernel,
                         cudaFuncAttributeMaxDynamicSharedMemorySize, SMEM_BYTES);
    encoder_kernel<<<BATCH, NT, SMEM_BYTES>>>(adjacency, node,
                                              W1, b1, V1, c1,
                                              W2, b2, V2, c2,
                                              Wi, bi, Wj, bj,
                                              (float*)d_out);
}